// round 7
// baseline (speedup 1.0000x reference)
#include <cuda_runtime.h>
#include <math.h>
#include <stdint.h>

typedef unsigned long long ull;

#define Bv 2
#define Nv 10000
#define Ev 160000
#define Hv 128
#define ETv 8
#define BN (Bv*Nv)
#define EPSv 1e-5f
#define RSQRT_H 0.08838834764831843f

#define APAD 130
#define SMEM_GEMM (2*128*APAD*4)   // 133120 bytes

// ---------------- scratch ----------------
__device__ float g_Q[BN*Hv];
__device__ float g_K[BN*Hv];
__device__ float g_V[BN*Hv];
__device__ float g_Agg[BN*Hv];
__device__ float g_Hmid[BN*Hv];
__device__ float g_segsum[BN];
__device__ float g_Ke[ETv*Hv];
__device__ float g_Ve[ETv*Hv];
__device__ float g_eL[ETv];

// ---------------- helpers ----------------
__device__ __forceinline__ void red_add_v4(float* p, float4 v) {
    asm volatile("red.global.add.v4.f32 [%0], {%1,%2,%3,%4};"
                 :: "l"(p), "f"(v.x), "f"(v.y), "f"(v.z), "f"(v.w) : "memory");
}
__device__ __forceinline__ void fma2(ull& d, ull a, ull b) {
    asm("fma.rn.f32x2 %0, %1, %2, %0;" : "+l"(d) : "l"(a), "l"(b));
}
__device__ __forceinline__ float hsum2(ull v) {
    unsigned a, b;
    asm("mov.b64 {%0, %1}, %2;" : "=r"(a), "=r"(b) : "l"(v));
    return __uint_as_float(a) + __uint_as_float(b);
}

// ---------------- 0: zero scratch ----------------
__global__ void zero_init() {
    int i = blockIdx.x * blockDim.x + threadIdx.x;
    int stride = gridDim.x * blockDim.x;
    for (int j = i; j < BN*Hv; j += stride) g_Agg[j] = 0.0f;
    for (int j = i; j < BN; j += stride) g_segsum[j] = 0.0f;
}

// ---------------- 1: edge-type projections ----------------
__global__ void prep_edge(const float* __restrict__ eemb,
                          const float* __restrict__ Wk,
                          const float* __restrict__ Wv,
                          const float* __restrict__ We,
                          const float* __restrict__ be) {
    int t = threadIdx.x >> 7;
    int j = threadIdx.x & 127;
    float ake = 0.f, ave = 0.f;
    #pragma unroll 4
    for (int k = 0; k < Hv; k++) {
        float e = eemb[t*Hv + k];
        ake += e * Wk[k*Hv + j];
        ave += e * Wv[k*Hv + j];
    }
    g_Ke[t*Hv + j] = ake;
    g_Ve[t*Hv + j] = ave;
    if (j == 0) {
        float s = 0.f;
        for (int k = 0; k < Hv; k++) s += eemb[t*Hv + k] * We[k];
        g_eL[t] = s + be[0];
    }
}

// ================= K-paired f32x2 GEMM framework =================
// Tile 128x128, 256 threads, 8x8 outputs/thread.
// rows: (tid>>4)*8 + r ; cols: c*16 + (tid&15)
// As[row][k] stride APAD ; Bs[col][k] = W[k][col] stride APAD.

__device__ __forceinline__ void stage_As(float* As, int tid, int row0,
                                         const float* __restrict__ s0,
                                         const float* __restrict__ s1,
                                         bool use_inv) {
    #pragma unroll
    for (int i = 0; i < 16; i++) {
        int e = tid + i * 256;
        int r = e >> 5, kk = (e & 31) * 4;
        int row = row0 + r;
        float4 a = make_float4(0.f, 0.f, 0.f, 0.f);
        if (row < BN) {
            a = *(const float4*)&s0[row * Hv + kk];
            if (s1) {
                float4 b = *(const float4*)&s1[row * Hv + kk];
                a.x += b.x; a.y += b.y; a.z += b.z; a.w += b.w;
            }
            if (use_inv) {
                float ssum = g_segsum[row];
                float inv = (ssum > 0.f) ? 1.f / ssum : 0.f;
                a.x *= inv; a.y *= inv; a.z *= inv; a.w *= inv;
            }
        }
        // APAD=130: index r*APAD+kk is always even -> 8B-aligned; use float2 stores
        *(float2*)&As[r * APAD + kk]     = make_float2(a.x, a.y);
        *(float2*)&As[r * APAD + kk + 2] = make_float2(a.z, a.w);
    }
}

// Bs[n][k] = W[k][n], W chunk is 128x128 row-major
__device__ __forceinline__ void stage_Bs(float* Bs, int tid,
                                         const float* __restrict__ W) {
    #pragma unroll
    for (int i = 0; i < 64; i++) {
        int e = tid + i * 256;
        int k = e >> 7, n = e & 127;
        Bs[n * APAD + k] = W[k * Hv + n];
    }
}

__device__ __forceinline__ void mm128(const float* As, const float* Bs,
                                      int rbase, int cg, ull acc[8][8]) {
    #pragma unroll 4
    for (int kp = 0; kp < 64; kp++) {
        int k2 = kp * 2;
        ull aa[8], bb[8];
        #pragma unroll
        for (int r = 0; r < 8; r++)
            aa[r] = *(const ull*)&As[(rbase + r) * APAD + k2];
        #pragma unroll
        for (int c = 0; c < 8; c++)
            bb[c] = *(const ull*)&Bs[(c * 16 + cg) * APAD + k2];
        #pragma unroll
        for (int r = 0; r < 8; r++)
            #pragma unroll
            for (int c = 0; c < 8; c++)
                fma2(acc[r][c], aa[r], bb[c]);
    }
}

// ---------------- 2: QKV GEMM (z selects Q/K/V) ----------------
__global__ void __launch_bounds__(256, 1)
gemm_qkv(const float* __restrict__ hidden, const float* __restrict__ temb,
         const float* __restrict__ Wq, const float* __restrict__ bq,
         const float* __restrict__ Wk, const float* __restrict__ bk,
         const float* __restrict__ Wv, const float* __restrict__ bv)
{
    extern __shared__ float sm[];
    float* As = sm;
    float* Bs = sm + 128 * APAD;
    int tid = threadIdx.x;
    int rbase = (tid >> 4) * 8, cg = tid & 15;
    int row0 = blockIdx.x * 128;
    int which = blockIdx.z;
    const float* W    = which == 0 ? Wq : (which == 1 ? Wk : Wv);
    const float* bias = which == 0 ? bq : (which == 1 ? bk : bv);
    float* out        = which == 0 ? g_Q : (which == 1 ? g_K : g_V);
    const float* s1   = (which < 2) ? temb : nullptr;

    stage_As(As, tid, row0, hidden, s1, false);
    stage_Bs(Bs, tid, W);
    __syncthreads();

    ull acc[8][8];
    #pragma unroll
    for (int r = 0; r < 8; r++)
        #pragma unroll
        for (int c = 0; c < 8; c++) acc[r][c] = 0ull;
    mm128(As, Bs, rbase, cg, acc);

    float bi[8];
    #pragma unroll
    for (int c = 0; c < 8; c++) bi[c] = __ldg(&bias[c * 16 + cg]);
    #pragma unroll
    for (int r = 0; r < 8; r++) {
        int row = row0 + rbase + r;
        if (row < BN) {
            #pragma unroll
            for (int c = 0; c < 8; c++)
                out[row * Hv + c * 16 + cg] = hsum2(acc[r][c]) + bi[c];
        }
    }
}

// ---------------- 3: FUSED edge kernel ----------------
__global__ void edge_fused(const int* __restrict__ eidx, const int* __restrict__ etype)
{
    int w = (blockIdx.x * blockDim.x + threadIdx.x) >> 5;
    int lane = threadIdx.x & 31;
    if (w >= Ev) return;
    int src = eidx[w];
    int tgt = eidx[Ev + w];
    int ty  = etype[w];
    float4 ke = *(const float4*)&g_Ke[ty*Hv + lane*4];
    float4 ve = *(const float4*)&g_Ve[ty*Hv + lane*4];
    float el = g_eL[ty];

    float4 q0 = *(const float4*)&g_Q[(0*Nv + tgt)*Hv + lane*4];
    float4 k0 = *(const float4*)&g_K[(0*Nv + src)*Hv + lane*4];
    float4 q1 = *(const float4*)&g_Q[(1*Nv + tgt)*Hv + lane*4];
    float4 k1 = *(const float4*)&g_K[(1*Nv + src)*Hv + lane*4];

    float s0 = q0.x*(k0.x+ke.x) + q0.y*(k0.y+ke.y) + q0.z*(k0.z+ke.z) + q0.w*(k0.w+ke.w);
    float s1 = q1.x*(k1.x+ke.x) + q1.y*(k1.y+ke.y) + q1.z*(k1.z+ke.z) + q1.w*(k1.w+ke.w);
    #pragma unroll
    for (int off = 16; off > 0; off >>= 1) {
        s0 += __shfl_xor_sync(0xffffffffu, s0, off);
        s1 += __shfl_xor_sync(0xffffffffu, s1, off);
    }
    float ex0 = expf(s0 * RSQRT_H + el);
    float ex1 = expf(s1 * RSQRT_H + el);
    if (lane == 0) {
        atomicAdd(&g_segsum[tgt], ex0);
        atomicAdd(&g_segsum[Nv + tgt], ex1);
    }
    float4 v0 = *(const float4*)&g_V[(0*Nv + src)*Hv + lane*4];
    float4 v1 = *(const float4*)&g_V[(1*Nv + src)*Hv + lane*4];
    float4 a0 = make_float4(ex0*(v0.x+ve.x), ex0*(v0.y+ve.y),
                            ex0*(v0.z+ve.z), ex0*(v0.w+ve.w));
    float4 a1 = make_float4(ex1*(v1.x+ve.x), ex1*(v1.y+ve.y),
                            ex1*(v1.z+ve.z), ex1*(v1.w+ve.w));
    red_add_v4(&g_Agg[(0*Nv + tgt)*Hv + lane*4], a0);
    red_add_v4(&g_Agg[(1*Nv + tgt)*Hv + lane*4], a1);
}

// ---------------- 4: MLP GEMM1 (3 K-chunks, SiLU) ----------------
__global__ void __launch_bounds__(256, 1)
gemm_mlp1(const float* __restrict__ hidden, const float* __restrict__ temb,
          const float* __restrict__ W1, const float* __restrict__ b1)
{
    extern __shared__ float sm[];
    float* As = sm;
    float* Bs = sm + 128 * APAD;
    int tid = threadIdx.x;
    int rbase = (tid >> 4) * 8, cg = tid & 15;
    int row0 = blockIdx.x * 128;

    ull acc[8][8];
    #pragma unroll
    for (int r = 0; r < 8; r++)
        #pragma unroll
        for (int c = 0; c < 8; c++) acc[r][c] = 0ull;

    for (int c3 = 0; c3 < 3; c3++) {
        const float* s0 = (c3 == 0) ? hidden : (c3 == 1 ? g_Agg : temb);
        stage_As(As, tid, row0, s0, nullptr, c3 == 1);
        stage_Bs(Bs, tid, W1 + c3 * 128 * Hv);
        __syncthreads();
        mm128(As, Bs, rbase, cg, acc);
        __syncthreads();
    }

    float bi[8];
    #pragma unroll
    for (int c = 0; c < 8; c++) bi[c] = __ldg(&b1[c * 16 + cg]);
    #pragma unroll
    for (int r = 0; r < 8; r++) {
        int row = row0 + rbase + r;
        if (row < BN) {
            #pragma unroll
            for (int c = 0; c < 8; c++) {
                float v = hsum2(acc[r][c]) + bi[c];
                v = v / (1.f + expf(-v));
                g_Hmid[row * Hv + c * 16 + cg] = v;
            }
        }
    }
}

// ---------------- 5: GEMM2 + residual + LayerNorm ----------------
__global__ void __launch_bounds__(256, 1)
gemm2_ln(const float* __restrict__ hidden,
         const float* __restrict__ W2, const float* __restrict__ b2,
         const float* __restrict__ gamma, const float* __restrict__ beta,
         float* __restrict__ out)
{
    extern __shared__ float sm[];
    float* As = sm;
    float* Bs = sm + 128 * APAD;
    int tid = threadIdx.x;
    int rbase = (tid >> 4) * 8, cg = tid & 15;
    int row0 = blockIdx.x * 128;

    stage_As(As, tid, row0, g_Hmid, nullptr, false);
    stage_Bs(Bs, tid, W2);
    __syncthreads();

    ull acc[8][8];
    #pragma unroll
    for (int r = 0; r < 8; r++)
        #pragma unroll
        for (int c = 0; c < 8; c++) acc[r][c] = 0ull;
    mm128(As, Bs, rbase, cg, acc);

    float b2v[8], gmv[8], btv[8];
    #pragma unroll
    for (int c = 0; c < 8; c++) {
        int col = c * 16 + cg;
        b2v[c] = __ldg(&b2[col]);
        gmv[c] = __ldg(&gamma[col]);
        btv[c] = __ldg(&beta[col]);
    }

    #pragma unroll
    for (int r = 0; r < 8; r++) {
        int row = row0 + rbase + r;
        float x[8];
        if (row < BN) {
            #pragma unroll
            for (int c = 0; c < 8; c++)
                x[c] = hsum2(acc[r][c]) + b2v[c]
                     + __ldg(&hidden[row * Hv + c * 16 + cg]);
        } else {
            #pragma unroll
            for (int c = 0; c < 8; c++) x[c] = 0.f;
        }
        float s = 0.f, ss = 0.f;
        #pragma unroll
        for (int c = 0; c < 8; c++) { s += x[c]; ss += x[c] * x[c]; }
        #pragma unroll
        for (int off = 8; off > 0; off >>= 1) {
            s  += __shfl_xor_sync(0xffffffffu, s, off);
            ss += __shfl_xor_sync(0xffffffffu, ss, off);
        }
        if (row < BN) {
            float mean = s * (1.f / 128.f);
            float var  = ss * (1.f / 128.f) - mean * mean;
            float rstd = rsqrtf(var + EPSv);
            #pragma unroll
            for (int c = 0; c < 8; c++)
                out[row * Hv + c * 16 + cg] =
                    (x[c] - mean) * rstd * gmv[c] + btv[c];
        }
    }
}

// ---------------- launch ----------------
extern "C" void kernel_launch(void* const* d_in, const int* in_sizes, int n_in,
                              void* d_out, int out_size)
{
    const float* hidden = (const float*)d_in[0];
    const float* temb   = (const float*)d_in[1];
    const int*   eidx   = (const int*)d_in[2];
    const int*   etype  = (const int*)d_in[3];
    const float* eemb   = (const float*)d_in[4];
    const float* Wq = (const float*)d_in[5];  const float* bq = (const float*)d_in[6];
    const float* Wk = (const float*)d_in[7];  const float* bk = (const float*)d_in[8];
    const float* Wv = (const float*)d_in[9];  const float* bv = (const float*)d_in[10];
    const float* We = (const float*)d_in[11]; const float* be = (const float*)d_in[12];
    const float* W1 = (const float*)d_in[13]; const float* b1 = (const float*)d_in[14];
    const float* W2 = (const float*)d_in[15]; const float* b2 = (const float*)d_in[16];
    const float* gamma = (const float*)d_in[17]; const float* beta = (const float*)d_in[18];
    float* out = (float*)d_out;

    cudaFuncSetAttribute(gemm_qkv,  cudaFuncAttributeMaxDynamicSharedMemorySize, SMEM_GEMM);
    cudaFuncSetAttribute(gemm_mlp1, cudaFuncAttributeMaxDynamicSharedMemorySize, SMEM_GEMM);
    cudaFuncSetAttribute(gemm2_ln,  cudaFuncAttributeMaxDynamicSharedMemorySize, SMEM_GEMM);

    int gb = (BN + 127) / 128;   // 157
    zero_init<<<2560, 256>>>();
    prep_edge<<<1, 1024>>>(eemb, Wk, Wv, We, be);
    dim3 gq(gb, 1, 3);
    gemm_qkv<<<gq, 256, SMEM_GEMM>>>(hidden, temb, Wq, bq, Wk, bk, Wv, bv);
    edge_fused<<<Ev/8, 256>>>(eidx, etype);
    gemm_mlp1<<<gb, 256, SMEM_GEMM>>>(hidden, temb, W1, b1);
    gemm2_ln<<<gb, 256, SMEM_GEMM>>>(hidden, W2, b2, gamma, beta, out);
}